// round 6
// baseline (speedup 1.0000x reference)
#include <cuda_runtime.h>
#include <cuda_bf16.h>
#include <cstdint>
#include <math.h>

#define BB   64
#define TT   512
#define DD   256
#define HH   512
#define NCTA 128
#define NTH  256

// ---------------------------------------------------------------------------
// Global scratch: split-bf16 planes (hi, lo) for x, out0, h.
// ---------------------------------------------------------------------------
__device__ __nv_bfloat16 g_xhi[TT * DD * BB];
__device__ __nv_bfloat16 g_xlo[TT * DD * BB];
__device__ __nv_bfloat16 g_o0hi[TT * HH * BB];
__device__ __nv_bfloat16 g_o0lo[TT * HH * BB];
__device__ __nv_bfloat16 g_hhi[2 * HH * BB];
__device__ __nv_bfloat16 g_hlo[2 * HH * BB];
__device__ unsigned g_bar_count;
__device__ unsigned g_bar_epoch;

// ---------------------------------------------------------------------------
// Tensor-core helpers
// ---------------------------------------------------------------------------
__device__ __forceinline__ void ldsm_x4(uint32_t (&r)[4], uint32_t addr) {
    asm volatile("ldmatrix.sync.aligned.m8n8.x4.shared.b16 {%0,%1,%2,%3}, [%4];\n"
                 : "=r"(r[0]), "=r"(r[1]), "=r"(r[2]), "=r"(r[3]) : "r"(addr));
}
__device__ __forceinline__ void ldsm_x2t(uint32_t (&r)[2], uint32_t addr) {
    asm volatile("ldmatrix.sync.aligned.m8n8.x2.trans.shared.b16 {%0,%1}, [%2];\n"
                 : "=r"(r[0]), "=r"(r[1]) : "r"(addr));
}
__device__ __forceinline__ void mma_bf16(float (&d)[4], const uint32_t (&a)[4],
                                         const uint32_t (&b)[2]) {
    asm volatile("mma.sync.aligned.m16n8k16.row.col.f32.bf16.bf16.f32 "
                 "{%0,%1,%2,%3}, {%4,%5,%6,%7}, {%8,%9}, {%0,%1,%2,%3};\n"
                 : "+f"(d[0]), "+f"(d[1]), "+f"(d[2]), "+f"(d[3])
                 : "r"(a[0]), "r"(a[1]), "r"(a[2]), "r"(a[3]),
                   "r"(b[0]), "r"(b[1]));
}
__device__ __forceinline__ void split_bf16(float v, __nv_bfloat16& hi, __nv_bfloat16& lo) {
    hi = __float2bfloat16_rn(v);
    lo = __float2bfloat16_rn(v - __bfloat162float(hi));
}

// ---------------------------------------------------------------------------
// Grid barrier (128 CTAs, 1 CTA/SM via smem, all co-resident; replay safe)
// ---------------------------------------------------------------------------
__device__ __forceinline__ void grid_barrier(int tid, unsigned& target) {
    __threadfence();
    __syncthreads();
    target += 1;
    if (tid == 0) {
        unsigned old = atomicAdd(&g_bar_count, 1u);
        if (old == NCTA - 1) {
            atomicExch(&g_bar_count, 0u);
            __threadfence();
            atomicAdd(&g_bar_epoch, 1u);
        } else {
            while ((int)(*(volatile unsigned*)&g_bar_epoch - target) < 0) {
                __nanosleep(32);
            }
            __threadfence();
        }
    }
    __syncthreads();
}

// ---------------------------------------------------------------------------
// Transpose + split x: [b][t][d] -> hi/lo planes [t][d][b]
// ---------------------------------------------------------------------------
__global__ void transpose_x_kernel(const float* __restrict__ x) {
    extern __shared__ float sm[];  // [256][65]
    const int t = blockIdx.x;
    const int tid = threadIdx.x;
    for (int i = tid; i < BB * DD; i += NTH) {
        int b = i >> 8;
        int d = i & 255;
        sm[d * 65 + b] = x[(size_t)b * (TT * DD) + (size_t)t * DD + d];
    }
    __syncthreads();
    const size_t base = (size_t)t * (DD * BB);
    for (int i = tid; i < DD * BB; i += NTH) {
        int d = i >> 6;
        int b = i & 63;
        float v = sm[d * 65 + b];
        __nv_bfloat16 hi, lo;
        split_bf16(v, hi, lo);
        g_xhi[base + i] = hi;
        g_xlo[base + i] = lo;
    }
}

// ---------------------------------------------------------------------------
// Persistent LSTM layer kernel, tensor-core split-bf16 inner GEMM.
// CTA owns 4 hidden units -> 16 gate rows (r = gate*4 + ul).
// D[16 rows x 64 batch]; 8 warps x 8 batches, full K per warp.
// K chunked by 128 with register-prefetch double-buffered staging.
// ---------------------------------------------------------------------------
template <int KX, int LAYER>
__global__ void lstm_layer_kernel(const float* __restrict__ W_ih,
                                  const float* __restrict__ W_hh,
                                  const float* __restrict__ b_ih,
                                  const float* __restrict__ b_hh,
                                  float* __restrict__ d_out) {
    constexpr int KTOT = KX + HH;
    constexpr int NCX  = KX / 128;
    constexpr int NCH  = KTOT / 128;
    extern __shared__ char smem_raw[];
    __nv_bfloat16* W_hi  = (__nv_bfloat16*)smem_raw;       // [KTOT/16][16][16]
    __nv_bfloat16* W_lo  = W_hi + KTOT * 16;
    __nv_bfloat16* st_hi = W_lo + KTOT * 16;               // [2][128][64]
    __nv_bfloat16* st_lo = st_hi + 2 * 128 * 64;
    float* gates  = (float*)(st_lo + 2 * 128 * 64);        // [16][64]
    float* c_s    = gates + 16 * 64;                       // [4][64]
    float* bias_s = c_s + 4 * 64;                          // [16]

    const int tid  = threadIdx.x;
    const int cta  = blockIdx.x;
    const int lane = tid & 31;
    const int b0   = (tid >> 5) * 8;

    // --- split + stage weights once: tile layout [k>>4][r][k&15] ---
    for (int i = tid; i < KTOT * 16; i += NTH) {
        int k = i >> 4;
        int r = i & 15;
        int j = (r >> 2) * HH + cta * 4 + (r & 3);
        float v = (k < KX) ? W_ih[(size_t)j * KX + k]
                           : W_hh[(size_t)j * HH + (k - KX)];
        __nv_bfloat16 hi, lo;
        split_bf16(v, hi, lo);
        int idx = (k >> 4) * 256 + r * 16 + (k & 15);
        W_hi[idx] = hi;
        W_lo[idx] = lo;
    }
    if (tid < 16) {
        int j = (tid >> 2) * HH + cta * 4 + (tid & 3);
        bias_s[tid] = b_ih[j] + b_hh[j];
    }
    c_s[tid] = 0.0f;
    {
        int ul = tid >> 6, b = tid & 63;
        g_hhi[(cta * 4 + ul) * BB + b] = __float2bfloat16_rn(0.0f);
        g_hlo[(cta * 4 + ul) * BB + b] = __float2bfloat16_rn(0.0f);
    }

    unsigned bar_target = 0;
    if (tid == 0) bar_target = *(volatile unsigned*)&g_bar_epoch;
    grid_barrier(tid, bar_target);

    const __nv_bfloat16* xhi = (LAYER == 0) ? g_xhi : g_o0hi;
    const __nv_bfloat16* xlo = (LAYER == 0) ? g_xlo : g_o0lo;

    const uint32_t sWhi = (uint32_t)__cvta_generic_to_shared(W_hi);
    const uint32_t sWlo = (uint32_t)__cvta_generic_to_shared(W_lo);
    const uint32_t sShi = (uint32_t)__cvta_generic_to_shared(st_hi);
    const uint32_t sSlo = (uint32_t)__cvta_generic_to_shared(st_lo);
    const uint32_t a_off = (uint32_t)((lane & 15) * 32 + (lane >> 4) * 16);
    const uint32_t b_row = (uint32_t)((lane & 15) * 128 + b0 * 2);

    for (int t = 0; t < TT; ++t) {
        const size_t xoff = (size_t)t * (KX * BB);
        const size_t hoff = (size_t)(t & 1) * (HH * BB);

        auto src_hi = [&](int c) -> const uint4* {
            return reinterpret_cast<const uint4*>(
                (c < NCX) ? (xhi + xoff + c * 8192) : (g_hhi + hoff + (c - NCX) * 8192));
        };
        auto src_lo = [&](int c) -> const uint4* {
            return reinterpret_cast<const uint4*>(
                (c < NCX) ? (xlo + xoff + c * 8192) : (g_hlo + hoff + (c - NCX) * 8192));
        };

        float acc[4] = {0.f, 0.f, 0.f, 0.f};

        uint4 pf_hi[4], pf_lo[4];
        {
            const uint4* gh = src_hi(0);
            const uint4* gl = src_lo(0);
            #pragma unroll
            for (int i = 0; i < 4; ++i) pf_hi[i] = __ldcg(gh + tid + i * NTH);
            #pragma unroll
            for (int i = 0; i < 4; ++i) pf_lo[i] = __ldcg(gl + tid + i * NTH);
            uint4* dh = reinterpret_cast<uint4*>(st_hi);
            uint4* dl = reinterpret_cast<uint4*>(st_lo);
            #pragma unroll
            for (int i = 0; i < 4; ++i) dh[tid + i * NTH] = pf_hi[i];
            #pragma unroll
            for (int i = 0; i < 4; ++i) dl[tid + i * NTH] = pf_lo[i];
        }
        __syncthreads();

        for (int c = 0; c < NCH; ++c) {
            const int cur = c & 1;
            if (c + 1 < NCH) {
                const uint4* gh = src_hi(c + 1);
                const uint4* gl = src_lo(c + 1);
                #pragma unroll
                for (int i = 0; i < 4; ++i) pf_hi[i] = __ldcg(gh + tid + i * NTH);
                #pragma unroll
                for (int i = 0; i < 4; ++i) pf_lo[i] = __ldcg(gl + tid + i * NTH);
            }

            const uint32_t stage_hi_b = sShi + cur * 16384;
            const uint32_t stage_lo_b = sSlo + cur * 16384;
            #pragma unroll
            for (int kt = 0; kt < 8; ++kt) {
                const uint32_t a_base = (uint32_t)((c * 8 + kt) * 512);
                uint32_t a_hi[4], a_lo[4], bq_hi[2], bq_lo[2];
                ldsm_x4(a_hi, sWhi + a_base + a_off);
                ldsm_x4(a_lo, sWlo + a_base + a_off);
                const uint32_t bbo = (uint32_t)(kt * 2048) + b_row;
                ldsm_x2t(bq_hi, stage_hi_b + bbo);
                ldsm_x2t(bq_lo, stage_lo_b + bbo);
                mma_bf16(acc, a_hi, bq_hi);
                mma_bf16(acc, a_hi, bq_lo);
                mma_bf16(acc, a_lo, bq_hi);
            }

            if (c + 1 < NCH) {
                uint4* dh = reinterpret_cast<uint4*>(st_hi) + (cur ^ 1) * 1024;
                uint4* dl = reinterpret_cast<uint4*>(st_lo) + (cur ^ 1) * 1024;
                #pragma unroll
                for (int i = 0; i < 4; ++i) dh[tid + i * NTH] = pf_hi[i];
                #pragma unroll
                for (int i = 0; i < 4; ++i) dl[tid + i * NTH] = pf_lo[i];
            }
            __syncthreads();
        }

        // --- scatter D fragments ---
        {
            const int row0 = lane >> 2;
            const int col0 = b0 + (lane & 3) * 2;
            gates[row0 * 64 + col0]           = acc[0];
            gates[row0 * 64 + col0 + 1]       = acc[1];
            gates[(row0 + 8) * 64 + col0]     = acc[2];
            gates[(row0 + 8) * 64 + col0 + 1] = acc[3];
        }
        __syncthreads();

        // --- cell update ---
        {
            const int ul = tid >> 6;
            const int b = tid & 63;
            const float gi = gates[(0 + ul) * 64 + b]  + bias_s[ul];
            const float gf = gates[(4 + ul) * 64 + b]  + bias_s[4 + ul];
            const float gg = gates[(8 + ul) * 64 + b]  + bias_s[8 + ul];
            const float go = gates[(12 + ul) * 64 + b] + bias_s[12 + ul];
            const float i_ = 1.0f / (1.0f + expf(-gi));
            const float f_ = 1.0f / (1.0f + expf(-gf));
            const float g_ = tanhf(gg);
            const float o_ = 1.0f / (1.0f + expf(-go));
            const float cn = f_ * c_s[ul * 64 + b] + i_ * g_;
            c_s[ul * 64 + b] = cn;
            const float h = o_ * tanhf(cn);
            const int col = cta * 4 + ul;
            __nv_bfloat16 hi, lo;
            split_bf16(h, hi, lo);
            const size_t ho = (size_t)((t + 1) & 1) * (HH * BB) + col * BB + b;
            g_hhi[ho] = hi;
            g_hlo[ho] = lo;
            if (LAYER == 0) {
                const size_t oo = (size_t)t * (HH * BB) + col * BB + b;
                g_o0hi[oo] = hi;
                g_o0lo[oo] = lo;
            }
            if (t == TT - 1) {
                d_out[64 + LAYER * (BB * HH) + (size_t)b * HH + col] = h;
                d_out[64 + 2 * (BB * HH) + LAYER * (BB * HH) + (size_t)b * HH + col] = cn;
            }
        }
        grid_barrier(tid, bar_target);
    }
}

// ---------------------------------------------------------------------------
// FC: out[b] = dot(hn1[b,:], fc_w) + fc_b
// ---------------------------------------------------------------------------
__global__ void fc_kernel(const float* __restrict__ fc_w,
                          const float* __restrict__ fc_b,
                          float* __restrict__ d_out) {
    const int b = blockIdx.x;
    const int tid = threadIdx.x;
    const float* h = d_out + 64 + (BB * HH) + (size_t)b * HH;
    float s = 0.0f;
    for (int k = tid; k < HH; k += 128) s += h[k] * fc_w[k];
    #pragma unroll
    for (int off = 16; off > 0; off >>= 1) s += __shfl_down_sync(0xffffffffu, s, off);
    __shared__ float wsum[4];
    if ((tid & 31) == 0) wsum[tid >> 5] = s;
    __syncthreads();
    if (tid == 0) d_out[b] = wsum[0] + wsum[1] + wsum[2] + wsum[3] + fc_b[0];
}

// ---------------------------------------------------------------------------
// Launch
// ---------------------------------------------------------------------------
extern "C" void kernel_launch(void* const* d_in, const int* in_sizes, int n_in,
                              void* d_out, int out_size) {
    const float* x     = (const float*)d_in[0];
    const float* W_ih0 = (const float*)d_in[1];
    const float* W_hh0 = (const float*)d_in[2];
    const float* b_ih0 = (const float*)d_in[3];
    const float* b_hh0 = (const float*)d_in[4];
    const float* W_ih1 = (const float*)d_in[5];
    const float* W_hh1 = (const float*)d_in[6];
    const float* b_ih1 = (const float*)d_in[7];
    const float* b_hh1 = (const float*)d_in[8];
    const float* fc_w  = (const float*)d_in[9];
    const float* fc_b  = (const float*)d_in[10];
    float* out = (float*)d_out;

    const int smem_tr = 256 * 65 * 4;
    const int smem_l0 = (256 + HH) * 16 * 2 * 2 + 2 * 128 * 64 * 2 * 2
                      + 16 * 64 * 4 + 4 * 64 * 4 + 16 * 4;
    const int smem_l1 = (512 + HH) * 16 * 2 * 2 + 2 * 128 * 64 * 2 * 2
                      + 16 * 64 * 4 + 4 * 64 * 4 + 16 * 4;

    cudaFuncSetAttribute(transpose_x_kernel,
                         cudaFuncAttributeMaxDynamicSharedMemorySize, smem_tr);
    cudaFuncSetAttribute(lstm_layer_kernel<256, 0>,
                         cudaFuncAttributeMaxDynamicSharedMemorySize, smem_l0);
    cudaFuncSetAttribute(lstm_layer_kernel<512, 1>,
                         cudaFuncAttributeMaxDynamicSharedMemorySize, smem_l1);

    transpose_x_kernel<<<TT, NTH, smem_tr>>>(x);
    lstm_layer_kernel<256, 0><<<NCTA, NTH, smem_l0>>>(W_ih0, W_hh0, b_ih0, b_hh0, out);
    lstm_layer_kernel<512, 1><<<NCTA, NTH, smem_l1>>>(W_ih1, W_hh1, b_ih1, b_hh1, out);
    fc_kernel<<<BB, 128>>>(fc_w, fc_b, out);
}

// round 8
// speedup vs baseline: 2.0854x; 2.0854x over previous
#include <cuda_runtime.h>
#include <cuda_bf16.h>
#include <cstdint>
#include <math.h>

#define BB   64
#define TT   512
#define DD   256
#define HH   512
#define NCTA 128
#define NGRP 64      // CTAs per barrier group (one per batch-group)
#define NTH  256

// ---------------------------------------------------------------------------
// Global scratch: split-bf16 planes (hi, lo). Row pitch = 64 batches.
// ---------------------------------------------------------------------------
__device__ __nv_bfloat16 g_xhi[TT * DD * BB];
__device__ __nv_bfloat16 g_xlo[TT * DD * BB];
__device__ __nv_bfloat16 g_o0hi[TT * HH * BB];
__device__ __nv_bfloat16 g_o0lo[TT * HH * BB];
__device__ __nv_bfloat16 g_hhi[2 * HH * BB];
__device__ __nv_bfloat16 g_hlo[2 * HH * BB];
__device__ unsigned g_bar_count[2];
__device__ unsigned g_bar_epoch[2];

// ---------------------------------------------------------------------------
// Tensor-core helpers
// ---------------------------------------------------------------------------
__device__ __forceinline__ void ldsm_x4(uint32_t (&r)[4], uint32_t addr) {
    asm volatile("ldmatrix.sync.aligned.m8n8.x4.shared.b16 {%0,%1,%2,%3}, [%4];\n"
                 : "=r"(r[0]), "=r"(r[1]), "=r"(r[2]), "=r"(r[3]) : "r"(addr));
}
__device__ __forceinline__ void ldsm_x2t(uint32_t (&r)[2], uint32_t addr) {
    asm volatile("ldmatrix.sync.aligned.m8n8.x2.trans.shared.b16 {%0,%1}, [%2];\n"
                 : "=r"(r[0]), "=r"(r[1]) : "r"(addr));
}
__device__ __forceinline__ void mma_bf16(float (&d)[4], const uint32_t (&a)[4],
                                         const uint32_t (&b)[2]) {
    asm volatile("mma.sync.aligned.m16n8k16.row.col.f32.bf16.bf16.f32 "
                 "{%0,%1,%2,%3}, {%4,%5,%6,%7}, {%8,%9}, {%0,%1,%2,%3};\n"
                 : "+f"(d[0]), "+f"(d[1]), "+f"(d[2]), "+f"(d[3])
                 : "r"(a[0]), "r"(a[1]), "r"(a[2]), "r"(a[3]),
                   "r"(b[0]), "r"(b[1]));
}
__device__ __forceinline__ void split_bf16(float v, __nv_bfloat16& hi, __nv_bfloat16& lo) {
    hi = __float2bfloat16_rn(v);
    lo = __float2bfloat16_rn(v - __bfloat162float(hi));
}

// ---------------------------------------------------------------------------
// Grouped grid barrier: NGRP=64 CTAs per group (all co-resident, 1 CTA/SM).
// ---------------------------------------------------------------------------
__device__ __forceinline__ void grid_barrier(int tid, int grp, unsigned& target) {
    __threadfence();
    __syncthreads();
    target += 1;
    if (tid == 0) {
        unsigned old = atomicAdd(&g_bar_count[grp], 1u);
        if (old == NGRP - 1) {
            atomicExch(&g_bar_count[grp], 0u);
            __threadfence();
            atomicAdd(&g_bar_epoch[grp], 1u);
        } else {
            while ((int)(*(volatile unsigned*)&g_bar_epoch[grp] - target) < 0) {
                __nanosleep(32);
            }
            __threadfence();
        }
    }
    __syncthreads();
}

// ---------------------------------------------------------------------------
// Transpose + split x: [b][t][d] -> hi/lo planes [t][d][b]
// ---------------------------------------------------------------------------
__global__ void transpose_x_kernel(const float* __restrict__ x) {
    extern __shared__ float sm[];  // [256][65]
    const int t = blockIdx.x;
    const int tid = threadIdx.x;
    for (int i = tid; i < BB * DD; i += NTH) {
        int b = i >> 8;
        int d = i & 255;
        sm[d * 65 + b] = x[(size_t)b * (TT * DD) + (size_t)t * DD + d];
    }
    __syncthreads();
    const size_t base = (size_t)t * (DD * BB);
    for (int i = tid; i < DD * BB; i += NTH) {
        int d = i >> 6;
        int b = i & 63;
        float v = sm[d * 65 + b];
        __nv_bfloat16 hi, lo;
        split_bf16(v, hi, lo);
        g_xhi[base + i] = hi;
        g_xlo[base + i] = lo;
    }
}

// ---------------------------------------------------------------------------
// Persistent LSTM layer kernel.
// Partition: 128 CTAs = 64 unit-groups (8 hidden units -> 32 gate rows,
// row rr = gate*8 + ul) x 2 batch-groups (32 batches).
// Warps K-split: warp w owns k-slice [w*16, w*16+16) of each 128-k chunk.
// A (weights) in smem tiles [16r][16k], XOR-swizzled, conflict-free ldsm_x4.
// B (activations) staged per chunk as [128k][32b], 64B pitch, XOR-swizzled,
// conflict-free ldsm_x2t. Split-bf16: 3 MMA products, fp32 accum.
// 8-warp partial reduction in smem, then fused cell update.
// ---------------------------------------------------------------------------
template <int KX, int LAYER>
__global__ __launch_bounds__(NTH)
void lstm_layer_kernel(const float* __restrict__ W_ih,
                       const float* __restrict__ W_hh,
                       const float* __restrict__ b_ih,
                       const float* __restrict__ b_hh,
                       float* __restrict__ d_out) {
    constexpr int KTOT = KX + HH;
    constexpr int NCX  = KX / 128;     // x chunks
    constexpr int NCH  = KTOT / 128;   // total chunks

    extern __shared__ char smem_raw[];
    __nv_bfloat16* W_hi  = (__nv_bfloat16*)smem_raw;        // KTOT*32 elems (tiles)
    __nv_bfloat16* W_lo  = W_hi + KTOT * 32;
    __nv_bfloat16* st_hi = W_lo + KTOT * 32;                // [2][128][32] (swizzled)
    __nv_bfloat16* st_lo = st_hi + 2 * 128 * 32;
    float* part   = (float*)(st_lo + 2 * 128 * 32);         // [8][32][32]
    float* gates  = part + 8 * 32 * 32;                     // [32][32]
    float* c_s    = gates + 32 * 32;                        // [8][32]
    float* bias_s = c_s + 8 * 32;                           // [32]

    const int tid  = threadIdx.x;
    const int ug   = blockIdx.x >> 1;   // unit group 0..63
    const int bg   = blockIdx.x & 1;    // batch group 0..1
    const int lane = tid & 31;
    const int w    = tid >> 5;          // warp id = k-slice

    // --- stage + split weights once; tile layout [c][w][mt][16r][16k] swizzled ---
    for (int i = tid; i < KTOT * 32; i += NTH) {
        int kcol = i & 15;
        int r    = (i >> 4) & 15;
        int mt   = (i >> 8) & 1;
        int ws   = (i >> 9) & 7;
        int c    = i >> 12;
        int rr   = mt * 16 + r;
        int gate = rr >> 3, ul = rr & 7;
        int kg   = c * 128 + ws * 16 + kcol;
        int j    = gate * HH + ug * 8 + ul;
        float v = (kg < KX) ? W_ih[(size_t)j * KX + kg]
                            : W_hh[(size_t)j * HH + (kg - KX)];
        __nv_bfloat16 hi, lo;
        split_bf16(v, hi, lo);
        int off = ((c * 8 + ws) * 2 + mt) * 512
                + r * 32
                + ((((unsigned)kcol >> 3) ^ (((unsigned)r >> 2) & 1u)) << 4)
                + (kcol & 7) * 2;
        *(__nv_bfloat16*)((char*)W_hi + off) = hi;
        *(__nv_bfloat16*)((char*)W_lo + off) = lo;
    }
    if (tid < 32) {
        int gate = tid >> 3, ul = tid & 7;
        int j = gate * HH + ug * 8 + ul;
        bias_s[tid] = b_ih[j] + b_hh[j];
    }
    c_s[tid] = 0.0f;
    {   // zero h planes (buf 0) for our (units, batch slice)
        int col = ug * 8 + (tid >> 5);
        int bgl = bg * 32 + (tid & 31);
        g_hhi[col * BB + bgl] = __float2bfloat16_rn(0.0f);
        g_hlo[col * BB + bgl] = __float2bfloat16_rn(0.0f);
    }

    unsigned bar_target = 0;
    if (tid == 0) bar_target = *(volatile unsigned*)&g_bar_epoch[bg];
    grid_barrier(tid, bg, bar_target);

    const __nv_bfloat16* xhi = (LAYER == 0) ? g_xhi : g_o0hi;
    const __nv_bfloat16* xlo = (LAYER == 0) ? g_xlo : g_o0lo;

    const uint32_t sWhi = (uint32_t)__cvta_generic_to_shared(W_hi);
    const uint32_t sWlo = (uint32_t)__cvta_generic_to_shared(W_lo);
    const uint32_t sShi = (uint32_t)__cvta_generic_to_shared(st_hi);
    const uint32_t sSlo = (uint32_t)__cvta_generic_to_shared(st_lo);

    // A lane address (within a 512B tile): row = lane&15, half = lane>>4
    const uint32_t a_off = (uint32_t)((lane & 15) * 32
                       + ((((unsigned)lane >> 4) ^ ((((unsigned)lane & 15) >> 2) & 1u)) << 4));
    // B lane row: warp's k-slice row
    const uint32_t krow = (uint32_t)(w * 16 + (lane & 15));
    const uint32_t bswz = (krow >> 1) & 3u;
    const uint32_t b_base = krow * 64;  // 64B pitch

    // staging task split: thread handles i = tid, tid+256; k = i>>2, g = i&3
    const int sk0 = tid >> 2, sg0 = tid & 3;
    const int sk1 = (tid + 256) >> 2, sg1 = (tid + 256) & 3;

    for (int t = 0; t < TT; ++t) {
        const size_t xoff = (size_t)t * (KX * BB);
        const size_t hoff = (size_t)(t & 1) * (HH * BB);

        auto src_hi = [&](int c) -> const __nv_bfloat16* {
            return (c < NCX) ? (xhi + xoff + (size_t)c * 128 * BB)
                             : (g_hhi + hoff + (size_t)(c - NCX) * 128 * BB);
        };
        auto src_lo = [&](int c) -> const __nv_bfloat16* {
            return (c < NCX) ? (xlo + xoff + (size_t)c * 128 * BB)
                             : (g_hlo + hoff + (size_t)(c - NCX) * 128 * BB);
        };
        // swizzled stage store offset for (k, granule)
        auto st_off = [&](int k, int g) -> int {
            return k * 64 + ((((unsigned)g) ^ (((unsigned)k >> 1) & 3u)) << 4);
        };

        float acc[2][4][4];
        #pragma unroll
        for (int mt = 0; mt < 2; ++mt)
            #pragma unroll
            for (int j = 0; j < 4; ++j)
                #pragma unroll
                for (int q = 0; q < 4; ++q) acc[mt][j][q] = 0.0f;

        // prime chunk 0 -> buf 0
        uint4 pf_hi[2], pf_lo[2];
        {
            const __nv_bfloat16* gh = src_hi(0);
            const __nv_bfloat16* gl = src_lo(0);
            pf_hi[0] = __ldcg((const uint4*)(gh + sk0 * BB + bg * 32) + sg0);
            pf_hi[1] = __ldcg((const uint4*)(gh + sk1 * BB + bg * 32) + sg1);
            pf_lo[0] = __ldcg((const uint4*)(gl + sk0 * BB + bg * 32) + sg0);
            pf_lo[1] = __ldcg((const uint4*)(gl + sk1 * BB + bg * 32) + sg1);
            *(uint4*)((char*)st_hi + st_off(sk0, sg0)) = pf_hi[0];
            *(uint4*)((char*)st_hi + st_off(sk1, sg1)) = pf_hi[1];
            *(uint4*)((char*)st_lo + st_off(sk0, sg0)) = pf_lo[0];
            *(uint4*)((char*)st_lo + st_off(sk1, sg1)) = pf_lo[1];
        }
        __syncthreads();

        for (int c = 0; c < NCH; ++c) {
            const int cur = c & 1;
            if (c + 1 < NCH) {
                const __nv_bfloat16* gh = src_hi(c + 1);
                const __nv_bfloat16* gl = src_lo(c + 1);
                pf_hi[0] = __ldcg((const uint4*)(gh + sk0 * BB + bg * 32) + sg0);
                pf_hi[1] = __ldcg((const uint4*)(gh + sk1 * BB + bg * 32) + sg1);
                pf_lo[0] = __ldcg((const uint4*)(gl + sk0 * BB + bg * 32) + sg0);
                pf_lo[1] = __ldcg((const uint4*)(gl + sk1 * BB + bg * 32) + sg1);
            }

            // B fragments: 4 n-tiles x 2 planes for this warp's 16-k rows
            uint32_t bhi[4][2], blo[4][2];
            const uint32_t sb_hi = sShi + cur * 8192 + b_base;
            const uint32_t sb_lo = sSlo + cur * 8192 + b_base;
            #pragma unroll
            for (int j = 0; j < 4; ++j) {
                const uint32_t go = ((uint32_t)j ^ bswz) << 4;
                ldsm_x2t(bhi[j], sb_hi + go);
                ldsm_x2t(blo[j], sb_lo + go);
            }

            // A tiles + MMA
            const uint32_t tile0 = (uint32_t)((c * 8 + w) * 1024);
            #pragma unroll
            for (int mt = 0; mt < 2; ++mt) {
                uint32_t ahi[4], alo[4];
                const uint32_t ta = tile0 + (uint32_t)mt * 512 + a_off;
                ldsm_x4(ahi, sWhi + ta);
                ldsm_x4(alo, sWlo + ta);
                #pragma unroll
                for (int j = 0; j < 4; ++j) {
                    mma_bf16(acc[mt][j], ahi, bhi[j]);
                    mma_bf16(acc[mt][j], ahi, blo[j]);
                    mma_bf16(acc[mt][j], alo, bhi[j]);
                }
            }

            if (c + 1 < NCH) {
                char* dh = (char*)st_hi + (cur ^ 1) * 8192;
                char* dl = (char*)st_lo + (cur ^ 1) * 8192;
                *(uint4*)(dh + st_off(sk0, sg0)) = pf_hi[0];
                *(uint4*)(dh + st_off(sk1, sg1)) = pf_hi[1];
                *(uint4*)(dl + st_off(sk0, sg0)) = pf_lo[0];
                *(uint4*)(dl + st_off(sk1, sg1)) = pf_lo[1];
            }
            __syncthreads();
        }

        // --- scatter warp partials: part[w][32r][32b] ---
        {
            const int row0 = lane >> 2;
            const int col0 = (lane & 3) * 2;
            float* pw = part + w * 1024;
            #pragma unroll
            for (int mt = 0; mt < 2; ++mt)
                #pragma unroll
                for (int j = 0; j < 4; ++j) {
                    float* p = pw + (mt * 16 + row0) * 32 + j * 8 + col0;
                    p[0]       = acc[mt][j][0];
                    p[1]       = acc[mt][j][1];
                    p[8 * 32]     = acc[mt][j][2];
                    p[8 * 32 + 1] = acc[mt][j][3];
                }
        }
        __syncthreads();

        // --- reduce 8 partials + bias -> gates[32][32] ---
        {
            const int row = tid >> 3;
            const int cg  = (tid & 7) << 2;
            float4 s = make_float4(0.f, 0.f, 0.f, 0.f);
            #pragma unroll
            for (int p = 0; p < 8; ++p) {
                const float4 v = *(const float4*)(part + p * 1024 + row * 32 + cg);
                s.x += v.x; s.y += v.y; s.z += v.z; s.w += v.w;
            }
            const float bias = bias_s[row];
            *(float4*)(gates + row * 32 + cg) =
                make_float4(s.x + bias, s.y + bias, s.z + bias, s.w + bias);
        }
        __syncthreads();

        // --- cell update: one thread per (unit, batch) ---
        {
            const int ul = tid >> 5;
            const int b  = tid & 31;
            const float gi = gates[(0  + ul) * 32 + b];
            const float gf = gates[(8  + ul) * 32 + b];
            const float gg = gates[(16 + ul) * 32 + b];
            const float go = gates[(24 + ul) * 32 + b];
            const float i_ = 1.0f / (1.0f + expf(-gi));
            const float f_ = 1.0f / (1.0f + expf(-gf));
            const float g_ = tanhf(gg);
            const float o_ = 1.0f / (1.0f + expf(-go));
            const float cn = f_ * c_s[tid] + i_ * g_;
            c_s[tid] = cn;
            const float h = o_ * tanhf(cn);
            const int col = ug * 8 + ul;
            const int bgl = bg * 32 + b;
            __nv_bfloat16 hi, lo;
            split_bf16(h, hi, lo);
            const size_t ho = (size_t)((t + 1) & 1) * (HH * BB) + col * BB + bgl;
            g_hhi[ho] = hi;
            g_hlo[ho] = lo;
            if (LAYER == 0) {
                const size_t oo = (size_t)t * (HH * BB) + col * BB + bgl;
                g_o0hi[oo] = hi;
                g_o0lo[oo] = lo;
            }
            if (t == TT - 1) {
                d_out[64 + LAYER * (BB * HH) + (size_t)bgl * HH + col] = h;
                d_out[64 + 2 * (BB * HH) + LAYER * (BB * HH) + (size_t)bgl * HH + col] = cn;
            }
        }
        grid_barrier(tid, bg, bar_target);
    }
}

// ---------------------------------------------------------------------------
// FC: out[b] = dot(hn1[b,:], fc_w) + fc_b
// ---------------------------------------------------------------------------
__global__ void fc_kernel(const float* __restrict__ fc_w,
                          const float* __restrict__ fc_b,
                          float* __restrict__ d_out) {
    const int b = blockIdx.x;
    const int tid = threadIdx.x;
    const float* h = d_out + 64 + (BB * HH) + (size_t)b * HH;
    float s = 0.0f;
    for (int k = tid; k < HH; k += 128) s += h[k] * fc_w[k];
    #pragma unroll
    for (int off = 16; off > 0; off >>= 1) s += __shfl_down_sync(0xffffffffu, s, off);
    __shared__ float wsum[4];
    if ((tid & 31) == 0) wsum[tid >> 5] = s;
    __syncthreads();
    if (tid == 0) d_out[b] = wsum[0] + wsum[1] + wsum[2] + wsum[3] + fc_b[0];
}

// ---------------------------------------------------------------------------
// Launch
// ---------------------------------------------------------------------------
extern "C" void kernel_launch(void* const* d_in, const int* in_sizes, int n_in,
                              void* d_out, int out_size) {
    const float* x     = (const float*)d_in[0];
    const float* W_ih0 = (const float*)d_in[1];
    const float* W_hh0 = (const float*)d_in[2];
    const float* b_ih0 = (const float*)d_in[3];
    const float* b_hh0 = (const float*)d_in[4];
    const float* W_ih1 = (const float*)d_in[5];
    const float* W_hh1 = (const float*)d_in[6];
    const float* b_ih1 = (const float*)d_in[7];
    const float* b_hh1 = (const float*)d_in[8];
    const float* fc_w  = (const float*)d_in[9];
    const float* fc_b  = (const float*)d_in[10];
    float* out = (float*)d_out;

    const int smem_tr = 256 * 65 * 4;
    // W(hi+lo) + stage(2 bufs, hi+lo) + part + gates + c + bias
    const int smem_l0 = (256 + HH) * 32 * 2 * 2 + 2 * 128 * 32 * 2 * 2
                      + 8 * 32 * 32 * 4 + 32 * 32 * 4 + 8 * 32 * 4 + 32 * 4;
    const int smem_l1 = (512 + HH) * 32 * 2 * 2 + 2 * 128 * 32 * 2 * 2
                      + 8 * 32 * 32 * 4 + 32 * 32 * 4 + 8 * 32 * 4 + 32 * 4;

    cudaFuncSetAttribute(transpose_x_kernel,
                         cudaFuncAttributeMaxDynamicSharedMemorySize, smem_tr);
    cudaFuncSetAttribute(lstm_layer_kernel<256, 0>,
                         cudaFuncAttributeMaxDynamicSharedMemorySize, smem_l0);
    cudaFuncSetAttribute(lstm_layer_kernel<512, 1>,
                         cudaFuncAttributeMaxDynamicSharedMemorySize, smem_l1);

    transpose_x_kernel<<<TT, NTH, smem_tr>>>(x);
    lstm_layer_kernel<256, 0><<<NCTA, NTH, smem_l0>>>(W_ih0, W_hh0, b_ih0, b_hh0, out);
    lstm_layer_kernel<512, 1><<<NCTA, NTH, smem_l1>>>(W_ih1, W_hh1, b_ih1, b_hh1, out);
    fc_kernel<<<BB, 128>>>(fc_w, fc_b, out);
}

// round 10
// speedup vs baseline: 2.6551x; 1.2732x over previous
#include <cuda_runtime.h>
#include <cuda_bf16.h>
#include <cstdint>
#include <math.h>

#define BB    64
#define TT    512
#define DD    256
#define HH    512
#define TTBB  (TT * BB)     // 32768
#define NCTA  128
#define NGRP  64
#define NTH   256

// ---------------------------------------------------------------------------
// Global scratch
// ---------------------------------------------------------------------------
__device__ __nv_bfloat16 g_xhi[DD * TTBB];      // x planes [d][t][b]
__device__ __nv_bfloat16 g_xlo[DD * TTBB];
__device__ __nv_bfloat16 g_o0hi[HH * TTBB];     // layer0 out planes [h][t][b]
__device__ __nv_bfloat16 g_o0lo[HH * TTBB];
__device__ __nv_bfloat16 g_hhi[2 * HH * BB];    // double-buffered h [buf][h][b]
__device__ __nv_bfloat16 g_hlo[2 * HH * BB];
__device__ __nv_bfloat16 g_wih0hi[4 * HH * DD]; // split W_ih planes
__device__ __nv_bfloat16 g_wih0lo[4 * HH * DD];
__device__ __nv_bfloat16 g_wih1hi[4 * HH * HH];
__device__ __nv_bfloat16 g_wih1lo[4 * HH * HH];
__device__ float g_xg0[(size_t)4 * HH * TTBB];  // xg [j][t][b] fp32 (256 MB)
__device__ float g_xg1[(size_t)4 * HH * TTBB];
__device__ unsigned g_bar_count[2];
__device__ unsigned g_bar_epoch[2];

// ---------------------------------------------------------------------------
// Helpers
// ---------------------------------------------------------------------------
__device__ __forceinline__ void ldsm_x4(uint32_t (&r)[4], uint32_t addr) {
    asm volatile("ldmatrix.sync.aligned.m8n8.x4.shared.b16 {%0,%1,%2,%3}, [%4];\n"
                 : "=r"(r[0]), "=r"(r[1]), "=r"(r[2]), "=r"(r[3]) : "r"(addr));
}
__device__ __forceinline__ void ldsm_x2t(uint32_t (&r)[2], uint32_t addr) {
    asm volatile("ldmatrix.sync.aligned.m8n8.x2.trans.shared.b16 {%0,%1}, [%2];\n"
                 : "=r"(r[0]), "=r"(r[1]) : "r"(addr));
}
__device__ __forceinline__ void mma_bf16(float (&d)[4], const uint32_t (&a)[4],
                                         const uint32_t (&b)[2]) {
    asm volatile("mma.sync.aligned.m16n8k16.row.col.f32.bf16.bf16.f32 "
                 "{%0,%1,%2,%3}, {%4,%5,%6,%7}, {%8,%9}, {%0,%1,%2,%3};\n"
                 : "+f"(d[0]), "+f"(d[1]), "+f"(d[2]), "+f"(d[3])
                 : "r"(a[0]), "r"(a[1]), "r"(a[2]), "r"(a[3]),
                   "r"(b[0]), "r"(b[1]));
}
__device__ __forceinline__ void split_bf16(float v, __nv_bfloat16& hi, __nv_bfloat16& lo) {
    hi = __float2bfloat16_rn(v);
    lo = __float2bfloat16_rn(v - __bfloat162float(hi));
}
__device__ __forceinline__ void cp_async16(uint32_t dst, const void* src) {
    asm volatile("cp.async.cg.shared.global [%0], [%1], 16;\n" :: "r"(dst), "l"(src));
}
__device__ __forceinline__ void cp_commit() {
    asm volatile("cp.async.commit_group;\n");
}
template <int N>
__device__ __forceinline__ void cp_wait() {
    asm volatile("cp.async.wait_group %0;\n" :: "n"(N));
}

// ---------------------------------------------------------------------------
// Grouped grid barrier (64 CTAs per group, all co-resident)
// ---------------------------------------------------------------------------
__device__ __forceinline__ void grid_barrier(int tid, int grp, unsigned& target) {
    __threadfence();
    __syncthreads();
    target += 1;
    if (tid == 0) {
        unsigned old = atomicAdd(&g_bar_count[grp], 1u);
        if (old == NGRP - 1) {
            atomicExch(&g_bar_count[grp], 0u);
            __threadfence();
            atomicAdd(&g_bar_epoch[grp], 1u);
        } else {
            while ((int)(*(volatile unsigned*)&g_bar_epoch[grp] - target) < 0) {
                __nanosleep(32);
            }
            __threadfence();
        }
    }
    __syncthreads();
}

// ---------------------------------------------------------------------------
// Split fp32 weight matrix into bf16 hi/lo planes
// ---------------------------------------------------------------------------
__global__ void split_w_kernel(const float* __restrict__ W,
                               __nv_bfloat16* __restrict__ hi,
                               __nv_bfloat16* __restrict__ lo, int n) {
    for (int i = blockIdx.x * blockDim.x + threadIdx.x; i < n; i += gridDim.x * blockDim.x) {
        __nv_bfloat16 h, l;
        split_bf16(W[i], h, l);
        hi[i] = h;
        lo[i] = l;
    }
}

// ---------------------------------------------------------------------------
// Transpose + split x: [b][t][d] -> planes [d][t][b]
// ---------------------------------------------------------------------------
__global__ void transpose_x_kernel(const float* __restrict__ x) {
    extern __shared__ float sm[];  // [256][65]
    const int t = blockIdx.x;
    const int tid = threadIdx.x;
    for (int i = tid; i < BB * DD; i += NTH) {
        int b = i >> 8;
        int d = i & 255;
        sm[d * 65 + b] = x[(size_t)b * (TT * DD) + (size_t)t * DD + d];
    }
    __syncthreads();
    for (int i = tid; i < DD * BB; i += NTH) {
        int d = i >> 6;
        int b = i & 63;
        float v = sm[d * 65 + b];
        __nv_bfloat16 hi, lo;
        split_bf16(v, hi, lo);
        const size_t idx = (size_t)d * TTBB + t * BB + b;
        g_xhi[idx] = hi;
        g_xlo[idx] = lo;
    }
}

// ---------------------------------------------------------------------------
// Bulk GEMM: C[j][n] = sum_k W[j][k] * X[k][n]   (j<2048, n<32768=t*64+b)
// Split-bf16, 3 products. CTA tile 128j x 128n, kc=32 chunks, cp.async
// double-buffered. 8 warps = 2(j) x 4(n); warp tile 64j x 32n.
// ---------------------------------------------------------------------------
template <int K>
__global__ __launch_bounds__(NTH)
void gemm_xg_kernel(const __nv_bfloat16* __restrict__ Whi,
                    const __nv_bfloat16* __restrict__ Wlo,
                    const __nv_bfloat16* __restrict__ Xhi,
                    const __nv_bfloat16* __restrict__ Xlo,
                    float* __restrict__ C) {
    constexpr int NKC = K / 32;
    extern __shared__ char sm_raw[];
    const uint32_t sbase = (uint32_t)__cvta_generic_to_shared(sm_raw);

    const int tid  = threadIdx.x;
    const int lane = tid & 31;
    const int w    = tid >> 5;
    const int wj   = w >> 2;          // 0..1
    const int wn0g = (w & 3) * 4;     // n granule base (granule = 8 cols)
    const int j0   = blockIdx.y * 128;
    const int n0   = blockIdx.x * 128;

    // buffer layout: [buf(2)]: Ahi 8KB | Alo 8KB | Bhi 8KB | Blo 8KB
    auto stage = [&](int kc, int buf) {
        const uint32_t bb = sbase + buf * 32768;
        #pragma unroll
        for (int q = 0; q < 4; ++q) {           // A: 1024 16B slots
            int idx = tid + q * 256;
            int p   = idx >> 9;
            int rem = idx & 511;
            int jl  = rem >> 2;
            int kh  = (rem >> 1) & 1;
            int g   = rem & 1;
            const __nv_bfloat16* src = (p ? Wlo : Whi)
                + (size_t)(j0 + jl) * K + kc * 32 + kh * 16 + g * 8;
            uint32_t dst = bb + p * 8192
                + (((jl >> 4) * 2 + kh) * 512)
                + (jl & 15) * 32
                + ((((unsigned)g) ^ (((unsigned)jl >> 2) & 1u)) << 4);
            cp_async16(dst, src);
        }
        #pragma unroll
        for (int q = 0; q < 4; ++q) {           // B: 1024 16B slots
            int idx = tid + q * 256;
            int p   = idx >> 9;
            int rem = idx & 511;
            int k   = rem >> 4;
            int g   = rem & 15;
            const __nv_bfloat16* src = (p ? Xlo : Xhi)
                + (size_t)(kc * 32 + k) * TTBB + n0 + g * 8;
            uint32_t dst = bb + 16384 + p * 8192 + k * 256
                + ((((unsigned)g) ^ ((unsigned)k & 7u)) << 4);
            cp_async16(dst, src);
        }
        cp_commit();
    };

    const uint32_t a_off = (uint32_t)((lane & 15) * 32
        + ((((unsigned)lane >> 4) ^ ((((unsigned)lane & 15) >> 2) & 1u)) << 4));

    float acc[4][4][4];
    #pragma unroll
    for (int mj = 0; mj < 4; ++mj)
        #pragma unroll
        for (int nj = 0; nj < 4; ++nj)
            #pragma unroll
            for (int q = 0; q < 4; ++q) acc[mj][nj][q] = 0.0f;

    stage(0, 0);
    for (int kc = 0; kc < NKC; ++kc) {
        if (kc + 1 < NKC) {
            stage(kc + 1, (kc + 1) & 1);
            cp_wait<1>();
        } else {
            cp_wait<0>();
        }
        __syncthreads();

        const uint32_t bb = sbase + (kc & 1) * 32768;
        const uint32_t Ahi_b = bb, Alo_b = bb + 8192;
        const uint32_t Bhi_b = bb + 16384, Blo_b = bb + 24576;

        #pragma unroll
        for (int kt = 0; kt < 2; ++kt) {
            uint32_t ahi[4][4], alo[4][4], bhi[4][2], blo[4][2];
            #pragma unroll
            for (int mj = 0; mj < 4; ++mj) {
                const uint32_t ta = (uint32_t)(((wj * 4 + mj) * 2 + kt) * 512) + a_off;
                ldsm_x4(ahi[mj], Ahi_b + ta);
                ldsm_x4(alo[mj], Alo_b + ta);
            }
            const uint32_t krow = (uint32_t)(kt * 16 + (lane & 15));
            #pragma unroll
            for (int nj = 0; nj < 4; ++nj) {
                const uint32_t go = (((uint32_t)(wn0g + nj)) ^ (krow & 7u)) << 4;
                ldsm_x2t(bhi[nj], Bhi_b + krow * 256 + go);
                ldsm_x2t(blo[nj], Blo_b + krow * 256 + go);
            }
            #pragma unroll
            for (int mj = 0; mj < 4; ++mj)
                #pragma unroll
                for (int nj = 0; nj < 4; ++nj) {
                    mma_bf16(acc[mj][nj], ahi[mj], bhi[nj]);
                    mma_bf16(acc[mj][nj], ahi[mj], blo[nj]);
                    mma_bf16(acc[mj][nj], alo[mj], bhi[nj]);
                }
        }
        __syncthreads();
    }

    // epilogue: direct STG (float2 per fragment half)
    #pragma unroll
    for (int mj = 0; mj < 4; ++mj) {
        const int jr = j0 + wj * 64 + mj * 16 + (lane >> 2);
        #pragma unroll
        for (int nj = 0; nj < 4; ++nj) {
            const int nc = n0 + (w & 3) * 32 + nj * 8 + (lane & 3) * 2;
            float2 v0 = make_float2(acc[mj][nj][0], acc[mj][nj][1]);
            float2 v1 = make_float2(acc[mj][nj][2], acc[mj][nj][3]);
            *(float2*)(C + (size_t)jr * TTBB + nc)       = v0;
            *(float2*)(C + (size_t)(jr + 8) * TTBB + nc) = v1;
        }
    }
}

// ---------------------------------------------------------------------------
// Recurrent kernel: gates = xg[t] + h @ W_hh^T + bias, cell update.
// 128 CTAs = 64 unit-groups (8 units -> 32 gate rows) x 2 batch-groups (32 b).
// K=512 (h only). All W_hh tiles + whole-h stage resident in smem:
// one staging burst + 4 chunk computes with no intermediate syncs.
// ---------------------------------------------------------------------------
template <int LAYER>
__global__ __launch_bounds__(NTH)
void lstm_rec_kernel(const float* __restrict__ W_hh,
                     const float* __restrict__ b_ih,
                     const float* __restrict__ b_hh,
                     const float* __restrict__ xg,
                     float* __restrict__ d_out) {
    extern __shared__ char smem_raw[];
    __nv_bfloat16* W_hi  = (__nv_bfloat16*)smem_raw;        // [4c][8w][2mt][512B]
    __nv_bfloat16* W_lo  = W_hi + HH * 32;
    __nv_bfloat16* st_hi = W_lo + HH * 32;                  // [512k][32b] swizzled
    __nv_bfloat16* st_lo = st_hi + HH * 32;
    float* part   = (float*)(st_lo + HH * 32);              // [8][32][32]
    float* gates  = part + 8 * 32 * 32;                     // [32][32]
    float* c_s    = gates + 32 * 32;                        // [8][32]
    float* bias_s = c_s + 8 * 32;                           // [32]

    const int tid  = threadIdx.x;
    const int ug   = blockIdx.x >> 1;
    const int bg   = blockIdx.x & 1;
    const int lane = tid & 31;
    const int w    = tid >> 5;

    // --- split + stage W_hh tiles once (same layout as proven R7 path) ---
    for (int i = tid; i < HH * 32; i += NTH) {
        int kcol = i & 15;
        int r    = (i >> 4) & 15;
        int mt   = (i >> 8) & 1;
        int ws   = (i >> 9) & 7;
        int c    = i >> 12;
        int rr   = mt * 16 + r;
        int gate = rr >> 3, ul = rr & 7;
        int kg   = c * 128 + ws * 16 + kcol;
        int j    = gate * HH + ug * 8 + ul;
        float v = W_hh[(size_t)j * HH + kg];
        __nv_bfloat16 hi, lo;
        split_bf16(v, hi, lo);
        int off = ((c * 8 + ws) * 2 + mt) * 512
                + r * 32
                + ((((unsigned)kcol >> 3) ^ (((unsigned)r >> 2) & 1u)) << 4)
                + (kcol & 7) * 2;
        *(__nv_bfloat16*)((char*)W_hi + off) = hi;
        *(__nv_bfloat16*)((char*)W_lo + off) = lo;
    }
    if (tid < 32) {
        int gate = tid >> 3, ul = tid & 7;
        int j = gate * HH + ug * 8 + ul;
        bias_s[tid] = b_ih[j] + b_hh[j];
    }
    c_s[tid] = 0.0f;
    {   // zero h buf 0 for our slice
        int col = ug * 8 + (tid >> 5);
        int bgl = bg * 32 + (tid & 31);
        g_hhi[col * BB + bgl] = __float2bfloat16_rn(0.0f);
        g_hlo[col * BB + bgl] = __float2bfloat16_rn(0.0f);
    }

    unsigned bar_target = 0;
    if (tid == 0) bar_target = *(volatile unsigned*)&g_bar_epoch[bg];
    grid_barrier(tid, bg, bar_target);

    const uint32_t sWhi = (uint32_t)__cvta_generic_to_shared(W_hi);
    const uint32_t sWlo = (uint32_t)__cvta_generic_to_shared(W_lo);
    const uint32_t sShi = (uint32_t)__cvta_generic_to_shared(st_hi);
    const uint32_t sSlo = (uint32_t)__cvta_generic_to_shared(st_lo);
    const uint32_t a_off = (uint32_t)((lane & 15) * 32
        + ((((unsigned)lane >> 4) ^ ((((unsigned)lane & 15) >> 2) & 1u)) << 4));

    // xg read slot (for reduce phase)
    const int xrow = tid >> 3;
    const int xcg  = (tid & 7) << 2;
    const int xj   = (xrow >> 3) * HH + ug * 8 + (xrow & 7);
    const float* xg_base = xg + (size_t)xj * TTBB + bg * 32 + xcg;

    for (int t = 0; t < TT; ++t) {
        // xg prefetch (no dependency on barrier)
        const float4 xg4 = __ldg((const float4*)(xg_base + t * BB));

        // --- stage whole h [512k][32b] hi/lo, one burst, MLP 16 ---
        const size_t hoff = (size_t)(t & 1) * (HH * BB);
        {
            uint4 vh[8], vl[8];
            #pragma unroll
            for (int q = 0; q < 8; ++q) {
                int s = tid + q * 256;
                int k = s >> 2, g = s & 3;
                const size_t so = hoff + (size_t)k * BB + bg * 32 + g * 8;
                vh[q] = __ldcg((const uint4*)(g_hhi + so));
                vl[q] = __ldcg((const uint4*)(g_hlo + so));
            }
            #pragma unroll
            for (int q = 0; q < 8; ++q) {
                int s = tid + q * 256;
                int k = s >> 2, g = s & 3;
                int off = k * 64 + ((((unsigned)g) ^ (((unsigned)k >> 1) & 3u)) << 4);
                *(uint4*)((char*)st_hi + off) = vh[q];
                *(uint4*)((char*)st_lo + off) = vl[q];
            }
        }
        __syncthreads();

        // --- 4 chunk computes, no syncs ---
        float acc[2][4][4];
        #pragma unroll
        for (int mt = 0; mt < 2; ++mt)
            #pragma unroll
            for (int j = 0; j < 4; ++j)
                #pragma unroll
                for (int q = 0; q < 4; ++q) acc[mt][j][q] = 0.0f;

        #pragma unroll
        for (int c = 0; c < 4; ++c) {
            const uint32_t kabs = (uint32_t)(c * 128 + w * 16 + (lane & 15));
            const uint32_t bswz = (kabs >> 1) & 3u;
            const uint32_t brow = kabs * 64;
            uint32_t bhi[4][2], blo[4][2];
            #pragma unroll
            for (int j = 0; j < 4; ++j) {
                const uint32_t go = (((uint32_t)j) ^ bswz) << 4;
                ldsm_x2t(bhi[j], sShi + brow + go);
                ldsm_x2t(blo[j], sSlo + brow + go);
            }
            const uint32_t tile0 = (uint32_t)((c * 8 + w) * 1024);
            #pragma unroll
            for (int mt = 0; mt < 2; ++mt) {
                uint32_t ahi[4], alo[4];
                const uint32_t ta = tile0 + (uint32_t)mt * 512 + a_off;
                ldsm_x4(ahi, sWhi + ta);
                ldsm_x4(alo, sWlo + ta);
                #pragma unroll
                for (int j = 0; j < 4; ++j) {
                    mma_bf16(acc[mt][j], ahi, bhi[j]);
                    mma_bf16(acc[mt][j], ahi, blo[j]);
                    mma_bf16(acc[mt][j], alo, bhi[j]);
                }
            }
        }
        __syncthreads();

        // --- scatter warp partials ---
        {
            const int row0 = lane >> 2;
            const int col0 = (lane & 3) * 2;
            float* pw = part + w * 1024;
            #pragma unroll
            for (int mt = 0; mt < 2; ++mt)
                #pragma unroll
                for (int j = 0; j < 4; ++j) {
                    float* p = pw + (mt * 16 + row0) * 32 + j * 8 + col0;
                    p[0]          = acc[mt][j][0];
                    p[1]          = acc[mt][j][1];
                    p[8 * 32]     = acc[mt][j][2];
                    p[8 * 32 + 1] = acc[mt][j][3];
                }
        }
        __syncthreads();

        // --- reduce 8 partials + xg + bias -> gates ---
        {
            float4 s = make_float4(xg4.x, xg4.y, xg4.z, xg4.w);
            #pragma unroll
            for (int p = 0; p < 8; ++p) {
                const float4 v = *(const float4*)(part + p * 1024 + xrow * 32 + xcg);
                s.x += v.x; s.y += v.y; s.z += v.z; s.w += v.w;
            }
            const float bias = bias_s[xrow];
            *(float4*)(gates + xrow * 32 + xcg) =
                make_float4(s.x + bias, s.y + bias, s.z + bias, s.w + bias);
        }
        __syncthreads();

        // --- cell update ---
        {
            const int ul = tid >> 5;
            const int b  = tid & 31;
            const float gi = gates[(0  + ul) * 32 + b];
            const float gf = gates[(8  + ul) * 32 + b];
            const float gg = gates[(16 + ul) * 32 + b];
            const float go = gates[(24 + ul) * 32 + b];
            const float i_ = 1.0f / (1.0f + expf(-gi));
            const float f_ = 1.0f / (1.0f + expf(-gf));
            const float g_ = tanhf(gg);
            const float o_ = 1.0f / (1.0f + expf(-go));
            const float cn = f_ * c_s[tid] + i_ * g_;
            c_s[tid] = cn;
            const float h = o_ * tanhf(cn);
            const int col = ug * 8 + ul;
            const int bgl = bg * 32 + b;
            __nv_bfloat16 hi, lo;
            split_bf16(h, hi, lo);
            const size_t ho = (size_t)((t + 1) & 1) * (HH * BB) + col * BB + bgl;
            g_hhi[ho] = hi;
            g_hlo[ho] = lo;
            if (LAYER == 0) {
                const size_t oo = (size_t)col * TTBB + t * BB + bgl;
                g_o0hi[oo] = hi;
                g_o0lo[oo] = lo;
            }
            if (t == TT - 1) {
                d_out[64 + LAYER * (BB * HH) + (size_t)bgl * HH + col] = h;
                d_out[64 + 2 * (BB * HH) + LAYER * (BB * HH) + (size_t)bgl * HH + col] = cn;
            }
        }
        grid_barrier(tid, bg, bar_target);
    }
}

// ---------------------------------------------------------------------------
// FC: out[b] = dot(hn1[b,:], fc_w) + fc_b
// ---------------------------------------------------------------------------
__global__ void fc_kernel(const float* __restrict__ fc_w,
                          const float* __restrict__ fc_b,
                          float* __restrict__ d_out) {
    const int b = blockIdx.x;
    const int tid = threadIdx.x;
    const float* h = d_out + 64 + (BB * HH) + (size_t)b * HH;
    float s = 0.0f;
    for (int k = tid; k < HH; k += 128) s += h[k] * fc_w[k];
    #pragma unroll
    for (int off = 16; off > 0; off >>= 1) s += __shfl_down_sync(0xffffffffu, s, off);
    __shared__ float wsum[4];
    if ((tid & 31) == 0) wsum[tid >> 5] = s;
    __syncthreads();
    if (tid == 0) d_out[b] = wsum[0] + wsum[1] + wsum[2] + wsum[3] + fc_b[0];
}

// ---------------------------------------------------------------------------
// Launch
// ---------------------------------------------------------------------------
extern "C" void kernel_launch(void* const* d_in, const int* in_sizes, int n_in,
                              void* d_out, int out_size) {
    const float* x     = (const float*)d_in[0];
    const float* W_ih0 = (const float*)d_in[1];
    const float* W_hh0 = (const float*)d_in[2];
    const float* b_ih0 = (const float*)d_in[3];
    const float* b_hh0 = (const float*)d_in[4];
    const float* W_ih1 = (const float*)d_in[5];
    const float* W_hh1 = (const float*)d_in[6];
    const float* b_ih1 = (const float*)d_in[7];
    const float* b_hh1 = (const float*)d_in[8];
    const float* fc_w  = (const float*)d_in[9];
    const float* fc_b  = (const float*)d_in[10];
    float* out = (float*)d_out;

    __nv_bfloat16 *wih0hi, *wih0lo, *wih1hi, *wih1lo, *xhi, *xlo, *o0hi, *o0lo;
    float *xg0, *xg1;
    cudaGetSymbolAddress((void**)&wih0hi, g_wih0hi);
    cudaGetSymbolAddress((void**)&wih0lo, g_wih0lo);
    cudaGetSymbolAddress((void**)&wih1hi, g_wih1hi);
    cudaGetSymbolAddress((void**)&wih1lo, g_wih1lo);
    cudaGetSymbolAddress((void**)&xhi, g_xhi);
    cudaGetSymbolAddress((void**)&xlo, g_xlo);
    cudaGetSymbolAddress((void**)&o0hi, g_o0hi);
    cudaGetSymbolAddress((void**)&o0lo, g_o0lo);
    cudaGetSymbolAddress((void**)&xg0, g_xg0);
    cudaGetSymbolAddress((void**)&xg1, g_xg1);

    const int smem_tr   = 256 * 65 * 4;
    const int smem_gemm = 65536;
    const int smem_rec  = HH * 32 * 2 * 2 * 2   // W + stage (hi/lo)
                        + 8 * 32 * 32 * 4 + 32 * 32 * 4 + 8 * 32 * 4 + 32 * 4;

    cudaFuncSetAttribute(transpose_x_kernel,
                         cudaFuncAttributeMaxDynamicSharedMemorySize, smem_tr);
    cudaFuncSetAttribute(gemm_xg_kernel<DD>,
                         cudaFuncAttributeMaxDynamicSharedMemorySize, smem_gemm);
    cudaFuncSetAttribute(gemm_xg_kernel<HH>,
                         cudaFuncAttributeMaxDynamicSharedMemorySize, smem_gemm);
    cudaFuncSetAttribute(lstm_rec_kernel<0>,
                         cudaFuncAttributeMaxDynamicSharedMemorySize, smem_rec);
    cudaFuncSetAttribute(lstm_rec_kernel<1>,
                         cudaFuncAttributeMaxDynamicSharedMemorySize, smem_rec);

    split_w_kernel<<<256, 256>>>(W_ih0, wih0hi, wih0lo, 4 * HH * DD);
    split_w_kernel<<<256, 256>>>(W_ih1, wih1hi, wih1lo, 4 * HH * HH);
    transpose_x_kernel<<<TT, NTH, smem_tr>>>(x);

    dim3 ggrid(TTBB / 128, 16);
    gemm_xg_kernel<DD><<<ggrid, NTH, smem_gemm>>>(wih0hi, wih0lo, xhi, xlo, xg0);
    lstm_rec_kernel<0><<<NCTA, NTH, smem_rec>>>(W_hh0, b_ih0, b_hh0, xg0, out);
    gemm_xg_kernel<HH><<<ggrid, NTH, smem_gemm>>>(wih1hi, wih1lo, o0hi, o0lo, xg1);
    lstm_rec_kernel<1><<<NCTA, NTH, smem_rec>>>(W_hh1, b_ih1, b_hh1, xg1, out);
    fc_kernel<<<BB, 128>>>(fc_w, fc_b, out);
}